// round 16
// baseline (speedup 1.0000x reference)
#include <cuda_runtime.h>
#include <math.h>

#define B 4
#define N 8192
#define M 8192
#define EPS 1e-8f
#define TSR 256   // source rows per CTA
#define TSC 128   // target cols per tile
#define NT  8     // col tiles swept per CTA
#define CGROUPS (M / (TSC * NT))   // 8 col groups
#define RTILES (N / TSR)           // 32

typedef unsigned long long u64;

__device__ float g_rowpart[B * CGROUPS * N];   // [b][colGroup][row]
__device__ float g_colpart[B * RTILES * M];    // [b][rowTile][col]
__device__ float g_bsum[256];

// ---------------- packed f32x2 helpers ----------------
__device__ __forceinline__ u64 pk2(float a, float b) {
    u64 r;
    asm("mov.b64 %0, {%1, %2};" : "=l"(r) : "f"(a), "f"(b));
    return r;
}
__device__ __forceinline__ u64 add2(u64 a, u64 b) {
    u64 r;
    asm("add.rn.f32x2 %0, %1, %2;" : "=l"(r) : "l"(a), "l"(b));
    return r;
}
__device__ __forceinline__ u64 fma2(u64 a, u64 b, u64 c) {
    u64 r;
    asm("fma.rn.f32x2 %0, %1, %2, %3;" : "=l"(r) : "l"(a), "l"(b), "l"(c));
    return r;
}
__device__ __forceinline__ float2 u2f(u64 v) {
    float2 f;
    asm("mov.b64 {%0, %1}, %2;" : "=f"(f.x), "=f"(f.y) : "l"(v));
    return f;
}

// ---------------- fused sweep kernel ----------------
// R15 structure (register-resident vertical source pairs, conflict-free target
// LDS, pipelined min-block) + NEW: two c-blocks (c and c+4) interleaved per
// warp — two independent fma chains and min streams in flight, doubling
// per-warp ILP to cover dependency stalls.
__global__ __launch_bounds__(256, 2) void tile_kernel(const float* __restrict__ source,
                                                      const float* __restrict__ target) {
    __shared__ __align__(16) float s_x[TSR], s_y[TSR], s_z[TSR], s_n[TSR];   // scalar source
    __shared__ __align__(16) u64 td_x[TSC], td_y[TSC], td_z[TSC], td_n[TSC]; // dup (-2t), (nt)
    __shared__ float red[TSR * 17];

    const int tid = threadIdx.x;
    const int b   = blockIdx.z;
    const int row0 = blockIdx.y * TSR;
    const int g    = blockIdx.x;
    const int colg0 = g * (TSC * NT);

    // Stage source (scalar): one row per thread
    {
        const float* sp = source + ((long)b * N + row0 + tid) * 3;
        float vx = sp[0], vy = sp[1], vz = sp[2];
        s_x[tid] = vx; s_y[tid] = vy; s_z[tid] = vz;
        s_n[tid] = vx * vx + vy * vy + vz * vz;
    }
    // Stage first target tile: duplicated pairs
    if (tid < TSC) {
        const float* tp = target + ((long)b * M + colg0 + tid) * 3;
        float vx = tp[0], vy = tp[1], vz = tp[2];
        td_x[tid] = pk2(-2.0f * vx, -2.0f * vx);
        td_y[tid] = pk2(-2.0f * vy, -2.0f * vy);
        td_z[tid] = pk2(-2.0f * vz, -2.0f * vz);
        float n = vx * vx + vy * vy + vz * vz;
        td_n[tid] = pk2(n, n);
    }
    __syncthreads();

    const int txi = tid & 15;
    const int tyi = tid >> 4;
    const int r0 = tyi * 16;  // this thread's 16 rows

    // Load source row-pairs into registers ONCE (LDS.64 of adjacent scalars)
    u64 px[8], py[8], pz[8], pn[8];
#pragma unroll
    for (int a = 0; a < 8; a++) {
        px[a] = *reinterpret_cast<const u64*>(&s_x[r0 + 2 * a]);
        py[a] = *reinterpret_cast<const u64*>(&s_y[r0 + 2 * a]);
        pz[a] = *reinterpret_cast<const u64*>(&s_z[r0 + 2 * a]);
        pn[a] = *reinterpret_cast<const u64*>(&s_n[r0 + 2 * a]);
    }

    const float BIGF = 3.4e38f;
    float rmin[16];
#pragma unroll
    for (int i = 0; i < 16; i++) rmin[i] = BIGF;

    float nx = 0.f, ny = 0.f, nz = 0.f;  // next-tile prefetch

    for (int ct = 0; ct < NT; ct++) {
        if (ct + 1 < NT && tid < TSC) {
            const float* tp = target + ((long)b * M + colg0 + (ct + 1) * TSC + tid) * 3;
            nx = tp[0]; ny = tp[1]; nz = tp[2];
        }

        // Two c-blocks in flight: columns cp*16+txi and (cp+4)*16+txi.
#pragma unroll
        for (int cp = 0; cp < 4; cp++) {
            const int colA = cp * 16 + txi;
            const int colB = (cp + 4) * 16 + txi;
            u64 txA = td_x[colA], tyA = td_y[colA], tzA = td_z[colA], tnA = td_n[colA];
            u64 txB = td_x[colB], tyB = td_y[colB], tzB = td_z[colB], tnB = td_n[colB];
            float cA0 = BIGF, cA1 = BIGF, cB0 = BIGF, cB1 = BIGF;

            u64 qpA, qpB;
            {
                u64 q = fma2(px[0], txA, add2(pn[0], tnA));
                q = fma2(py[0], tyA, q);
                qpA = fma2(pz[0], tzA, q);
                u64 r = fma2(px[0], txB, add2(pn[0], tnB));
                r = fma2(py[0], tyB, r);
                qpB = fma2(pz[0], tzB, r);
            }
#pragma unroll
            for (int a = 1; a < 8; a++) {
                // chain A for row-pair a
                u64 qA = fma2(px[a], txA, add2(pn[a], tnA));
                qA = fma2(py[a], tyA, qA);
                qA = fma2(pz[a], tzA, qA);
                // consume A from a-1
                {
                    float2 f = u2f(qpA);
                    rmin[2 * (a - 1)]     = fminf(rmin[2 * (a - 1)], f.x);
                    rmin[2 * (a - 1) + 1] = fminf(rmin[2 * (a - 1) + 1], f.y);
                    cA0 = fminf(cA0, f.x); cA1 = fminf(cA1, f.y);
                }
                // chain B for row-pair a
                u64 qB = fma2(px[a], txB, add2(pn[a], tnB));
                qB = fma2(py[a], tyB, qB);
                qB = fma2(pz[a], tzB, qB);
                // consume B from a-1
                {
                    float2 f = u2f(qpB);
                    rmin[2 * (a - 1)]     = fminf(rmin[2 * (a - 1)], f.x);
                    rmin[2 * (a - 1) + 1] = fminf(rmin[2 * (a - 1) + 1], f.y);
                    cB0 = fminf(cB0, f.x); cB1 = fminf(cB1, f.y);
                }
                qpA = qA; qpB = qB;
            }
            // drain a=7 (both chains)
            {
                float2 f = u2f(qpA);
                rmin[14] = fminf(rmin[14], f.x);
                rmin[15] = fminf(rmin[15], f.y);
                cA0 = fminf(cA0, f.x); cA1 = fminf(cA1, f.y);
            }
            {
                float2 f = u2f(qpB);
                rmin[14] = fminf(rmin[14], f.x);
                rmin[15] = fminf(rmin[15], f.y);
                cB0 = fminf(cB0, f.x); cB1 = fminf(cB1, f.y);
            }
            red[colA * 17 + tyi] = fminf(cA0, cA1);
            red[colB * 17 + tyi] = fminf(cB0, cB1);
        }
        __syncthreads();
        // col-min reduction across tyi (16 values per col)
        if (tid < TSC) {
            float m = red[tid * 17];
#pragma unroll
            for (int k = 1; k < 16; k++) m = fminf(m, red[tid * 17 + k]);
            g_colpart[((long)b * RTILES + blockIdx.y) * M + colg0 + ct * TSC + tid] = m;
        }
        __syncthreads();

        // Commit prefetched target tile
        if (ct + 1 < NT) {
            if (tid < TSC) {
                td_x[tid] = pk2(-2.0f * nx, -2.0f * nx);
                td_y[tid] = pk2(-2.0f * ny, -2.0f * ny);
                td_z[tid] = pk2(-2.0f * nz, -2.0f * nz);
                float n = nx * nx + ny * ny + nz * nz;
                td_n[tid] = pk2(n, n);
            }
            __syncthreads();
        }
    }

    // ---- row-min reduction (across txi), once per CTA ----
#pragma unroll
    for (int i = 0; i < 16; i++) red[(r0 + i) * 17 + txi] = rmin[i];
    __syncthreads();
    {
        float m = red[tid * 17];
#pragma unroll
        for (int k = 1; k < 16; k++) m = fminf(m, red[tid * 17 + k]);
        g_rowpart[((long)b * CGROUPS + g) * N + row0 + tid] = m;
    }
}

// ---------------- finalize pass 1: reduce partials, block sums ----------------
__global__ void finalize1_kernel(const float* __restrict__ weights) {
    __shared__ float sred[256];
    int tid = blockIdx.x * blockDim.x + threadIdx.x;
    float v;
    if (tid < B * N) {
        int b = tid >> 13, row = tid & 8191;
        const float* p = &g_rowpart[((long)b * CGROUPS) * N + row];
        float m = p[0];
#pragma unroll 8
        for (int ct = 1; ct < CGROUPS; ct++) m = fminf(m, p[(long)ct * N]);
        v = sqrtf(m + EPS) * weights[tid] * (1.0f / (B * N));
    } else {
        int t = tid - B * N;
        int b = t >> 13, col = t & 8191;
        const float* p = &g_colpart[((long)b * RTILES) * M + col];
        float m = p[0];
#pragma unroll 8
        for (int rt = 1; rt < RTILES; rt++) m = fminf(m, p[(long)rt * M]);
        v = sqrtf(m + EPS) * (1.0f / (B * M));
    }
    sred[threadIdx.x] = v;
    __syncthreads();
    for (int s = 128; s > 0; s >>= 1) {
        if (threadIdx.x < s) sred[threadIdx.x] += sred[threadIdx.x + s];
        __syncthreads();
    }
    if (threadIdx.x == 0) g_bsum[blockIdx.x] = sred[0];
}

// ---------------- finalize pass 2: single block, plain store ----------------
__global__ void finalize2_kernel(float* __restrict__ out) {
    __shared__ float sred[256];
    sred[threadIdx.x] = g_bsum[threadIdx.x];
    __syncthreads();
    for (int s = 128; s > 0; s >>= 1) {
        if (threadIdx.x < s) sred[threadIdx.x] += sred[threadIdx.x + s];
        __syncthreads();
    }
    if (threadIdx.x == 0) out[0] = sred[0];
}

extern "C" void kernel_launch(void* const* d_in, const int* in_sizes, int n_in,
                              void* d_out, int out_size) {
    const float* source  = (const float*)d_in[0];
    const float* target  = (const float*)d_in[1];
    const float* weights = (const float*)d_in[2];
    float* out = (float*)d_out;

    dim3 grid(CGROUPS, RTILES, B);
    tile_kernel<<<grid, 256>>>(source, target);

    finalize1_kernel<<<(B * N + B * M) / 256, 256>>>(weights);
    finalize2_kernel<<<1, 256>>>(out);
}

// round 17
// speedup vs baseline: 1.0316x; 1.0316x over previous
#include <cuda_runtime.h>
#include <math.h>

#define B 4
#define N 8192
#define M 8192
#define EPS 1e-8f
#define TSR 256   // source rows per CTA
#define TSC 128   // target cols per tile
#define NT  8     // col tiles swept per CTA
#define CGROUPS (M / (TSC * NT))   // 8 col groups
#define RTILES (N / TSR)           // 32

typedef unsigned long long u64;

__device__ float g_rowpart[B * CGROUPS * N];   // [b][colGroup][row]
__device__ float g_colpart[B * RTILES * M];    // [b][rowTile][col]
__device__ float g_bsum[256];

// ---------------- packed f32x2 helpers ----------------
__device__ __forceinline__ u64 pk2(float a, float b) {
    u64 r;
    asm("mov.b64 %0, {%1, %2};" : "=l"(r) : "f"(a), "f"(b));
    return r;
}
__device__ __forceinline__ u64 add2(u64 a, u64 b) {
    u64 r;
    asm("add.rn.f32x2 %0, %1, %2;" : "=l"(r) : "l"(a), "l"(b));
    return r;
}
__device__ __forceinline__ u64 fma2(u64 a, u64 b, u64 c) {
    u64 r;
    asm("fma.rn.f32x2 %0, %1, %2, %3;" : "=l"(r) : "l"(a), "l"(b), "l"(c));
    return r;
}
__device__ __forceinline__ float2 u2f(u64 v) {
    float2 f;
    asm("mov.b64 {%0, %1}, %2;" : "=f"(f.x), "=f"(f.y) : "l"(v));
    return f;
}

// ---------------- fused sweep kernel ----------------
// R15 structure (register-resident vertical source pairs, conflict-free target
// LDS) + dual-stream a-loop: rows a and a+4 of the SAME column interleaved
// (two independent fma chains sharing one td set -> +2 regs only). Target
// prefetch moved out of the compute loop (liveness -3 regs; latency overlaps
// the reduction barriers).
__global__ __launch_bounds__(256, 2) void tile_kernel(const float* __restrict__ source,
                                                      const float* __restrict__ target) {
    __shared__ __align__(16) float s_x[TSR], s_y[TSR], s_z[TSR], s_n[TSR];   // scalar source
    __shared__ __align__(16) u64 td_x[TSC], td_y[TSC], td_z[TSC], td_n[TSC]; // dup (-2t), (nt)
    __shared__ float red[TSR * 17];

    const int tid = threadIdx.x;
    const int b   = blockIdx.z;
    const int row0 = blockIdx.y * TSR;
    const int g    = blockIdx.x;
    const int colg0 = g * (TSC * NT);

    // Stage source (scalar): one row per thread
    {
        const float* sp = source + ((long)b * N + row0 + tid) * 3;
        float vx = sp[0], vy = sp[1], vz = sp[2];
        s_x[tid] = vx; s_y[tid] = vy; s_z[tid] = vz;
        s_n[tid] = vx * vx + vy * vy + vz * vz;
    }
    // Stage first target tile: duplicated pairs
    if (tid < TSC) {
        const float* tp = target + ((long)b * M + colg0 + tid) * 3;
        float vx = tp[0], vy = tp[1], vz = tp[2];
        td_x[tid] = pk2(-2.0f * vx, -2.0f * vx);
        td_y[tid] = pk2(-2.0f * vy, -2.0f * vy);
        td_z[tid] = pk2(-2.0f * vz, -2.0f * vz);
        float n = vx * vx + vy * vy + vz * vz;
        td_n[tid] = pk2(n, n);
    }
    __syncthreads();

    const int txi = tid & 15;
    const int tyi = tid >> 4;
    const int r0 = tyi * 16;  // this thread's 16 rows

    // Load source row-pairs into registers ONCE (LDS.64 of adjacent scalars)
    u64 px[8], py[8], pz[8], pn[8];
#pragma unroll
    for (int a = 0; a < 8; a++) {
        px[a] = *reinterpret_cast<const u64*>(&s_x[r0 + 2 * a]);
        py[a] = *reinterpret_cast<const u64*>(&s_y[r0 + 2 * a]);
        pz[a] = *reinterpret_cast<const u64*>(&s_z[r0 + 2 * a]);
        pn[a] = *reinterpret_cast<const u64*>(&s_n[r0 + 2 * a]);
    }

    const float BIGF = 3.4e38f;
    float rmin[16];
#pragma unroll
    for (int i = 0; i < 16; i++) rmin[i] = BIGF;

    for (int ct = 0; ct < NT; ct++) {
#pragma unroll
        for (int c = 0; c < 8; c++) {
            const int col = c * 16 + txi;   // unit stride across lanes: conflict-free
            u64 tx = td_x[col], ty = td_y[col], tz = td_z[col], tn = td_n[col];
            float cA0 = BIGF, cA1 = BIGF, cB0 = BIGF, cB1 = BIGF;

            // Two independent streams over 'a': A = pairs 0..3, B = pairs 4..7.
            u64 qpA, qpB;
            {
                u64 q = fma2(px[0], tx, add2(pn[0], tn));
                q = fma2(py[0], ty, q);
                qpA = fma2(pz[0], tz, q);
                u64 r = fma2(px[4], tx, add2(pn[4], tn));
                r = fma2(py[4], ty, r);
                qpB = fma2(pz[4], tz, r);
            }
#pragma unroll
            for (int k = 1; k < 4; k++) {
                // chain A for pair k
                u64 qA = fma2(px[k], tx, add2(pn[k], tn));
                qA = fma2(py[k], ty, qA);
                qA = fma2(pz[k], tz, qA);
                // consume A from pair k-1 (rows 2k-2, 2k-1)
                {
                    float2 f = u2f(qpA);
                    rmin[2 * k - 2] = fminf(rmin[2 * k - 2], f.x);
                    rmin[2 * k - 1] = fminf(rmin[2 * k - 1], f.y);
                    cA0 = fminf(cA0, f.x); cA1 = fminf(cA1, f.y);
                }
                // chain B for pair k+4
                u64 qB = fma2(px[k + 4], tx, add2(pn[k + 4], tn));
                qB = fma2(py[k + 4], ty, qB);
                qB = fma2(pz[k + 4], tz, qB);
                // consume B from pair k+3 (rows 2k+6, 2k+7)
                {
                    float2 f = u2f(qpB);
                    rmin[2 * k + 6] = fminf(rmin[2 * k + 6], f.x);
                    rmin[2 * k + 7] = fminf(rmin[2 * k + 7], f.y);
                    cB0 = fminf(cB0, f.x); cB1 = fminf(cB1, f.y);
                }
                qpA = qA; qpB = qB;
            }
            // drain: A holds pair 3 (rows 6,7); B holds pair 7 (rows 14,15)
            {
                float2 f = u2f(qpA);
                rmin[6] = fminf(rmin[6], f.x);
                rmin[7] = fminf(rmin[7], f.y);
                cA0 = fminf(cA0, f.x); cA1 = fminf(cA1, f.y);
            }
            {
                float2 f = u2f(qpB);
                rmin[14] = fminf(rmin[14], f.x);
                rmin[15] = fminf(rmin[15], f.y);
                cB0 = fminf(cB0, f.x); cB1 = fminf(cB1, f.y);
            }
            red[col * 17 + tyi] = fminf(fminf(cA0, cA1), fminf(cB0, cB1));
        }

        // Prefetch next tile AFTER compute (latency overlaps reduction barriers;
        // keeps the prefetch registers dead during the hot loop).
        float nx = 0.f, ny = 0.f, nz = 0.f;
        if (ct + 1 < NT && tid < TSC) {
            const float* tp = target + ((long)b * M + colg0 + (ct + 1) * TSC + tid) * 3;
            nx = tp[0]; ny = tp[1]; nz = tp[2];
        }
        __syncthreads();
        // col-min reduction across tyi (16 values per col)
        if (tid < TSC) {
            float m = red[tid * 17];
#pragma unroll
            for (int k = 1; k < 16; k++) m = fminf(m, red[tid * 17 + k]);
            g_colpart[((long)b * RTILES + blockIdx.y) * M + colg0 + ct * TSC + tid] = m;
        }
        __syncthreads();

        // Commit prefetched target tile
        if (ct + 1 < NT) {
            if (tid < TSC) {
                td_x[tid] = pk2(-2.0f * nx, -2.0f * nx);
                td_y[tid] = pk2(-2.0f * ny, -2.0f * ny);
                td_z[tid] = pk2(-2.0f * nz, -2.0f * nz);
                float n = nx * nx + ny * ny + nz * nz;
                td_n[tid] = pk2(n, n);
            }
            __syncthreads();
        }
    }

    // ---- row-min reduction (across txi), once per CTA ----
#pragma unroll
    for (int i = 0; i < 16; i++) red[(r0 + i) * 17 + txi] = rmin[i];
    __syncthreads();
    {
        float m = red[tid * 17];
#pragma unroll
        for (int k = 1; k < 16; k++) m = fminf(m, red[tid * 17 + k]);
        g_rowpart[((long)b * CGROUPS + g) * N + row0 + tid] = m;
    }
}

// ---------------- finalize pass 1: reduce partials, block sums ----------------
__global__ void finalize1_kernel(const float* __restrict__ weights) {
    __shared__ float sred[256];
    int tid = blockIdx.x * blockDim.x + threadIdx.x;
    float v;
    if (tid < B * N) {
        int b = tid >> 13, row = tid & 8191;
        const float* p = &g_rowpart[((long)b * CGROUPS) * N + row];
        float m = p[0];
#pragma unroll 8
        for (int ct = 1; ct < CGROUPS; ct++) m = fminf(m, p[(long)ct * N]);
        v = sqrtf(m + EPS) * weights[tid] * (1.0f / (B * N));
    } else {
        int t = tid - B * N;
        int b = t >> 13, col = t & 8191;
        const float* p = &g_colpart[((long)b * RTILES) * M + col];
        float m = p[0];
#pragma unroll 8
        for (int rt = 1; rt < RTILES; rt++) m = fminf(m, p[(long)rt * M]);
        v = sqrtf(m + EPS) * (1.0f / (B * M));
    }
    sred[threadIdx.x] = v;
    __syncthreads();
    for (int s = 128; s > 0; s >>= 1) {
        if (threadIdx.x < s) sred[threadIdx.x] += sred[threadIdx.x + s];
        __syncthreads();
    }
    if (threadIdx.x == 0) g_bsum[blockIdx.x] = sred[0];
}

// ---------------- finalize pass 2: single block, plain store ----------------
__global__ void finalize2_kernel(float* __restrict__ out) {
    __shared__ float sred[256];
    sred[threadIdx.x] = g_bsum[threadIdx.x];
    __syncthreads();
    for (int s = 128; s > 0; s >>= 1) {
        if (threadIdx.x < s) sred[threadIdx.x] += sred[threadIdx.x + s];
        __syncthreads();
    }
    if (threadIdx.x == 0) out[0] = sred[0];
}

extern "C" void kernel_launch(void* const* d_in, const int* in_sizes, int n_in,
                              void* d_out, int out_size) {
    const float* source  = (const float*)d_in[0];
    const float* target  = (const float*)d_in[1];
    const float* weights = (const float*)d_in[2];
    float* out = (float*)d_out;

    dim3 grid(CGROUPS, RTILES, B);
    tile_kernel<<<grid, 256>>>(source, target);

    finalize1_kernel<<<(B * N + B * M) / 256, 256>>>(weights);
    finalize2_kernel<<<1, 256>>>(out);
}